// round 9
// baseline (speedup 1.0000x reference)
#include <cuda_runtime.h>
#include <cuda_fp16.h>

#define N_TOK 16384
#define E_DIM 64
#define NHEAD 8
#define SEQ   1024
#define NBATCH 16

typedef unsigned long long U64;
typedef unsigned U32;

// scratch: fp16 Q/K/V in attention-native layouts
__device__ U32 g_q[NBATCH * NHEAD * SEQ * 4];  // [b][h][q][dimpair]  (pre-scaled)
__device__ U32 g_k[NBATCH * NHEAD * SEQ * 4];  // [b][h][key][dimpair]
__device__ U32 g_v[NBATCH * NHEAD * 8 * 512];  // [b][h][dim][keypair]
__device__ float g_o[N_TOK * E_DIM];

// ---------------- helpers ----------------
__device__ __forceinline__ U64 pack2(float a, float b) {
    U64 r;
    asm("mov.b64 %0, {%1,%2};" : "=l"(r) : "f"(a), "f"(b));
    return r;
}
__device__ __forceinline__ void unpack2(U64 v, float& a, float& b) {
    asm("mov.b64 {%0,%1}, %2;" : "=f"(a), "=f"(b) : "l"(v));
}
__device__ __forceinline__ U64 fma2(U64 a, U64 b, U64 c) {
    U64 d;
    asm("fma.rn.f32x2 %0, %1, %2, %3;" : "=l"(d) : "l"(a), "l"(b), "l"(c));
    return d;
}
__device__ __forceinline__ U32 f2h2(float hi, float lo) {  // lo -> low half
    U32 r;
    asm("cvt.rn.f16x2.f32 %0, %1, %2;" : "=r"(r) : "f"(hi), "f"(lo));
    return r;
}
__device__ __forceinline__ U32 h2ex2(U32 x) {
    U32 r;
    asm("ex2.approx.f16x2 %0, %1;" : "=r"(r) : "r"(x));
    return r;
}
__device__ __forceinline__ U32 hadd2(U32 a, U32 b) {
    U32 r;
    asm("add.rn.f16x2 %0, %1, %2;" : "=r"(r) : "r"(a), "r"(b));
    return r;
}
__device__ __forceinline__ void h2tof(U32 h, float& lo, float& hi) {
    asm("{.reg .f16 l, m; mov.b32 {l, m}, %2; cvt.f32.f16 %0, l; cvt.f32.f16 %1, m;}"
        : "=f"(lo), "=f"(hi) : "r"(h));
}
__device__ __forceinline__ U32 prmt(U32 a, U32 b, U32 sel) {
    U32 r;
    asm("prmt.b32 %0, %1, %2, %3;" : "=r"(r) : "r"(a), "r"(b), "r"(sel));
    return r;
}
// QK^T: m16n8k8, f16 inputs + f16 accumulators (C=0).
__device__ __forceinline__ void mma_qk_h(U32& d0, U32& d1, U32 a0, U32 a1, U32 b0) {
    asm("mma.sync.aligned.m16n8k8.row.col.f16.f16.f16.f16 "
        "{%0,%1},{%2,%3},{%4},{%5,%6};"
        : "=r"(d0), "=r"(d1)
        : "r"(a0), "r"(a1), "r"(b0), "r"(0u), "r"(0u));
}
// m16n8k16 f16 inputs, f32 accum (accumulating in place)
__device__ __forceinline__ void mma_16816(float& c0, float& c1, float& c2, float& c3,
                                          U32 a0, U32 a1, U32 a2, U32 a3, U32 b0, U32 b1) {
    asm("mma.sync.aligned.m16n8k16.row.col.f32.f16.f16.f32 "
        "{%0,%1,%2,%3},{%4,%5,%6,%7},{%8,%9},{%0,%1,%2,%3};"
        : "+f"(c0), "+f"(c1), "+f"(c2), "+f"(c3)
        : "r"(a0), "r"(a1), "r"(a2), "r"(a3), "r"(b0), "r"(b1));
}

// ================= Kernel 1: QKV projection via HMMA (unchanged) =================
#define QKV_SMEM ((128 * 36 + 96 * 36 + 128 * 35) * 4 + 192 * 4)
__global__ void __launch_bounds__(512) k_qkv(const float* __restrict__ x,
                                             const float* __restrict__ W,
                                             const float* __restrict__ bias) {
    extern __shared__ U32 smq[];
    U32* xh = smq;
    U32* wh = xh + 128 * 36;
    U32* vst = wh + 96 * 36;
    float* bs = (float*)(vst + 128 * 35);

    int tid = threadIdx.x;
    int warp = tid >> 5, lane = tid & 31;
    int rwarp = warp & 7, nthalf = warp >> 3;
    int g = lane >> 2, c = lane & 3;
    int y = blockIdx.y;
    int rowbase = blockIdx.x * 128;
    int bt = rowbase >> 10;
    int qloc = rowbase & 1023;

    const float4* x4 = (const float4*)x;
    for (int idx = tid; idx < 2048; idx += 512) {
        int row = idx >> 4, k4 = idx & 15;
        float4 v = x4[(long)(rowbase + row) * 16 + k4];
        xh[row * 36 + 2 * k4] = f2h2(v.y, v.x);
        xh[row * 36 + 2 * k4 + 1] = f2h2(v.w, v.z);
    }
    const float4* W4 = (const float4*)W;
    for (int idx = tid; idx < 1536; idx += 512) {
        int cc = idx >> 4, k4 = idx & 15;
        float4 v = W4[(y * 96 + cc) * 16 + k4];
        wh[cc * 36 + 2 * k4] = f2h2(v.y, v.x);
        wh[cc * 36 + 2 * k4 + 1] = f2h2(v.w, v.z);
    }
    if (tid < 192) bs[tid] = bias[tid];
    __syncthreads();

    int wr0 = rwarp * 16 + g, wr1 = wr0 + 8;
    U32 a[4][4];
#pragma unroll
    for (int ks = 0; ks < 4; ks++) {
        a[ks][0] = xh[wr0 * 36 + ks * 8 + c];
        a[ks][1] = xh[wr1 * 36 + ks * 8 + c];
        a[ks][2] = xh[wr0 * 36 + ks * 8 + c + 4];
        a[ks][3] = xh[wr1 * 36 + ks * 8 + c + 4];
    }

    const float SCL2 = 0.51010927915195162f;
#pragma unroll 1
    for (int ntl2 = 0; ntl2 < 6; ntl2++) {
        int ntl = nthalf * 6 + ntl2;
        int nt = y * 12 + ntl;
        float c0 = 0.f, c1 = 0.f, c2 = 0.f, c3 = 0.f;
        int ncol = ntl * 8 + g;
#pragma unroll
        for (int ks = 0; ks < 4; ks++) {
            U32 b0 = wh[ncol * 36 + ks * 8 + c];
            U32 b1 = wh[ncol * 36 + ks * 8 + c + 4];
            mma_16816(c0, c1, c2, c3, a[ks][0], a[ks][1], a[ks][2], a[ks][3], b0, b1);
        }
        int col0 = nt * 8 + 2 * c;
        float bv0 = bs[col0], bv1 = bs[col0 + 1];
        c0 += bv0; c1 += bv1; c2 += bv0; c3 += bv1;
        if (nt < 8) {
            long base = ((long)(bt * 8 + nt) * 1024 + qloc);
            g_q[(base + wr0) * 4 + c] = f2h2(c1 * SCL2, c0 * SCL2);
            g_q[(base + wr1) * 4 + c] = f2h2(c3 * SCL2, c2 * SCL2);
        } else if (nt < 16) {
            long base = ((long)(bt * 8 + (nt - 8)) * 1024 + qloc);
            g_k[(base + wr0) * 4 + c] = f2h2(c1, c0);
            g_k[(base + wr1) * 4 + c] = f2h2(c3, c2);
        } else {
            vst[wr0 * 35 + (nt - 16) * 4 + c] = f2h2(c1, c0);
            vst[wr1 * 35 + (nt - 16) * 4 + c] = f2h2(c3, c2);
        }
    }
    if (y == 1) {
        __syncthreads();
        int kpbase = qloc >> 1;
        for (int idx = tid; idx < 4096; idx += 512) {
            int d = idx >> 6, t = idx & 63;
            U32 w0 = vst[(2 * t) * 35 + (d >> 1)];
            U32 w1 = vst[(2 * t + 1) * 35 + (d >> 1)];
            U32 o = (d & 1) ? prmt(w0, w1, 0x7632u) : prmt(w0, w1, 0x5410u);
            g_v[((long)(bt * 8 + (d >> 3)) * 8 + (d & 7)) * 512 + kpbase + t] = o;
        }
    }
}

// ================= Kernel 2: attention (minimal 3-HMMA loop) =================
// 1024 CTAs: (b, h, qtile of 128). 256 threads = 8 warps x 16 queries.
#define ATTN_SMEM (1024 * 16 + 8 * 516 * 4)
__global__ void __launch_bounds__(256) k_attn() {
    extern __shared__ U32 smA[];
    U32* Ku = smA;            // [1024 key][4 words]
    U32* Vu = smA + 4096;     // [8 dim][516 keypair words]

    int tid = threadIdx.x;
    int warp = tid >> 5, lane = tid & 31;
    int g = lane >> 2, c = lane & 3;

    int bid = blockIdx.x;
    int b = bid >> 6;
    int h = (bid >> 3) & 7;
    int qt = bid & 7;

    const uint4* Ksrc = (const uint4*)(g_k + (long)(b * 8 + h) * 4096);
    const uint4* Vsrc = (const uint4*)(g_v + (long)(b * 8 + h) * 4096);
#pragma unroll
    for (int i = tid; i < 1024; i += 256) {
        ((uint4*)Ku)[i] = Ksrc[i];
        uint4 v = Vsrc[i];
        int dim = i >> 7, kp = (i & 127) << 2;
        *(uint4*)(Vu + dim * 516 + kp) = v;
    }

    int qloc0 = qt * 128 + warp * 16 + g;
    int qloc1 = qloc0 + 8;
    long qb = (long)(b * 8 + h) * 1024;
    U32 aq0 = g_q[(qb + qloc0) * 4 + c];
    U32 aq1 = g_q[(qb + qloc1) * 4 + c];

    float acc0 = 0.f, acc1 = 0.f, acc2 = 0.f, acc3 = 0.f;
    float lA = 0.f, lB = 0.f;
    __syncthreads();

    const U32* Kg = Ku + g * 4 + c;
    const U32* Vg = Vu + g * 516 + c;
#pragma unroll 1
    for (int jo = 0; jo < 8; jo++) {
        U32 lu = 0, lv = 0;
#pragma unroll
        for (int ji = 0; ji < 8; ji++) {
            int n = jo * 128 + ji * 16;
            U32 kb0 = Kg[n * 4];
            U32 kb1 = Kg[(n + 8) * 4];
            U32 s0, s1, s2, s3;
            mma_qk_h(s0, s1, aq0, aq1, kb0);
            mma_qk_h(s2, s3, aq0, aq1, kb1);
            U32 p0 = h2ex2(s0);  // row g,   keys n+2c, n+2c+1
            U32 p1 = h2ex2(s1);  // row g+8
            U32 p2 = h2ex2(s2);  // row g,   keys n+8+2c, +1
            U32 p3 = h2ex2(s3);  // row g+8
            lu = hadd2(lu, hadd2(p0, p2));
            lv = hadd2(lv, hadd2(p1, p3));
            U32 vb0 = Vg[n >> 1];
            U32 vb1 = Vg[(n >> 1) + 4];
            mma_16816(acc0, acc1, acc2, acc3, p0, p1, p2, p3, vb0, vb1);
        }
        float flo, fhi;
        h2tof(lu, flo, fhi);
        lA += flo + fhi;
        h2tof(lv, flo, fhi);
        lB += flo + fhi;
    }

    lA += __shfl_xor_sync(0xffffffffu, lA, 1);
    lA += __shfl_xor_sync(0xffffffffu, lA, 2);
    lB += __shfl_xor_sync(0xffffffffu, lB, 1);
    lB += __shfl_xor_sync(0xffffffffu, lB, 2);
    float invA = __fdividef(1.0f, lA);
    float invB = __fdividef(1.0f, lB);

    int r0 = b * SEQ + qloc0, r1 = b * SEQ + qloc1;
    float2* og0 = (float2*)(g_o + (long)r0 * 64 + 8 * h);
    float2* og1 = (float2*)(g_o + (long)r1 * 64 + 8 * h);
    og0[c] = make_float2(acc0 * invA, acc1 * invA);
    og1[c] = make_float2(acc2 * invB, acc3 * invB);
}

// ================= Kernel 3: fused tail — 64 rows/CTA, 2 CTAs/SM =================
// grid 256, 256 threads = 8 warps x 8 rows. w1/w2 stored fp16 (scalar cvt on load).
// SMEM floats: wo[64*65]=4160 | w1h 4224 | w2h 4160 | bb 512 | tT[64k][68]=4352 | hT[128k][68]=8704
#define TAIL_SMEM ((4160 + 4224 + 4160 + 512 + 4352 + 8704) * 4)
__global__ void __launch_bounds__(256) k_tail(
    const float* __restrict__ x, const float* __restrict__ Wout, const float* __restrict__ bout,
    const float* __restrict__ g1, const float* __restrict__ be1, const float* __restrict__ g2,
    const float* __restrict__ be2, const float* __restrict__ Wm1, const float* __restrict__ bm1,
    const float* __restrict__ Wm2, const float* __restrict__ bm2, float* __restrict__ out) {
    extern __shared__ float sm[];
    float* wo = sm;                       // [64 c][65]
    __half* w1h = (__half*)(sm + 4160);   // [128 h][66] halves
    __half* w2h = (__half*)(sm + 8384);   // [64 c][130] halves
    float* bb = sm + 12544;               // 512
    float* tT = bb + 512;                 // [64 k][68], rows 0..63 (o, then mi)
    float* hT = tT + 4352;                // [128 k][68]

    int tid = threadIdx.x;
    int warp = tid >> 5, lane = tid & 31;
    int rowbase = blockIdx.x * 64;

    {
        const float4* Wo = (const float4*)Wout;
        for (int idx = tid; idx < 64 * 16; idx += 256) {
            int cc = idx >> 4, k4 = idx & 15;
            float4 v = Wo[idx];
            wo[cc * 65 + 4 * k4 + 0] = v.x; wo[cc * 65 + 4 * k4 + 1] = v.y;
            wo[cc * 65 + 4 * k4 + 2] = v.z; wo[cc * 65 + 4 * k4 + 3] = v.w;
        }
        const float4* W1 = (const float4*)Wm1;
        for (int idx = tid; idx < 128 * 16; idx += 256) {
            int cc = idx >> 4, k4 = idx & 15;
            float4 v = W1[idx];
            U32* dst = (U32*)(w1h + cc * 66);
            dst[2 * k4] = f2h2(v.y, v.x);
            dst[2 * k4 + 1] = f2h2(v.w, v.z);
        }
        const float4* W2 = (const float4*)Wm2;
        for (int idx = tid; idx < 64 * 32; idx += 256) {
            int cc = idx >> 5, k4 = idx & 31;
            float4 v = W2[idx];
            U32* dst = (U32*)(w2h + cc * 130);
            dst[2 * k4] = f2h2(v.y, v.x);
            dst[2 * k4 + 1] = f2h2(v.w, v.z);
        }
        if (tid < 64) bb[tid] = bout[tid];
        if (tid < 128) bb[64 + tid] = bm1[tid];
        if (tid < 64) {
            bb[192 + tid] = bm2[tid];
            bb[256 + tid] = g1[tid];
            bb[320 + tid] = be1[tid];
            bb[384 + tid] = g2[tid];
            bb[448 + tid] = be2[tid];
        }
        const float4* o4 = (const float4*)g_o;
        for (int idx = tid; idx < 64 * 16; idx += 256) {
            int row = idx >> 4, k4 = idx & 15;
            float4 v = o4[(long)(rowbase + row) * 16 + k4];
            tT[(4 * k4 + 0) * 68 + row] = v.x;
            tT[(4 * k4 + 1) * 68 + row] = v.y;
            tT[(4 * k4 + 2) * 68 + row] = v.z;
            tT[(4 * k4 + 3) * 68 + row] = v.w;
        }
    }
    __syncthreads();

    int c0 = lane, c1 = lane + 32;
    const float* trow = tT + warp * 8;

    // ---- out-proj (8 rows x 2 cols, f32 weights) ----
    U64 acc[4][2];
#pragma unroll
    for (int p = 0; p < 4; p++) { acc[p][0] = 0ull; acc[p][1] = 0ull; }
#pragma unroll 4
    for (int k = 0; k < 64; k++) {
        const U64* xp = (const U64*)(trow + k * 68);
        float w0 = wo[c0 * 65 + k], w1v = wo[c1 * 65 + k];
        U64 w0p = pack2(w0, w0), w1p = pack2(w1v, w1v);
#pragma unroll
        for (int p = 0; p < 4; p++) {
            U64 xv = xp[p];
            acc[p][0] = fma2(xv, w0p, acc[p][0]);
            acc[p][1] = fma2(xv, w1p, acc[p][1]);
        }
    }
    __syncthreads();

    // residual + bias + LN1 -> miT (reuse tT)
    float bo0 = bb[c0], bo1 = bb[c1];
    float ga0 = bb[256 + c0], ga1 = bb[256 + c1];
    float bt0 = bb[320 + c0], bt1 = bb[320 + c1];
#pragma unroll
    for (int p = 0; p < 4; p++) {
        int ra = rowbase + warp * 8 + 2 * p;
        float t0a, t0b, t1a, t1b;
        unpack2(acc[p][0], t0a, t0b);
        unpack2(acc[p][1], t1a, t1b);
        t0a += bo0 + x[(long)ra * 64 + c0];
        t1a += bo1 + x[(long)ra * 64 + c1];
        t0b += bo0 + x[(long)(ra + 1) * 64 + c0];
        t1b += bo1 + x[(long)(ra + 1) * 64 + c1];
        float sa = t0a + t1a, qa = t0a * t0a + t1a * t1a;
        float sb = t0b + t1b, qb = t0b * t0b + t1b * t1b;
#pragma unroll
        for (int off = 16; off; off >>= 1) {
            sa += __shfl_xor_sync(0xffffffffu, sa, off);
            qa += __shfl_xor_sync(0xffffffffu, qa, off);
            sb += __shfl_xor_sync(0xffffffffu, sb, off);
            qb += __shfl_xor_sync(0xffffffffu, qb, off);
        }
        float ma = sa * (1.f / 64.f), mb = sb * (1.f / 64.f);
        float rsa = rsqrtf(qa * (1.f / 64.f) - ma * ma + 1e-5f);
        float rsb = rsqrtf(qb * (1.f / 64.f) - mb * mb + 1e-5f);
        int rla = warp * 8 + 2 * p;
        tT[c0 * 68 + rla] = (t0a - ma) * rsa * ga0 + bt0;
        tT[c1 * 68 + rla] = (t1a - ma) * rsa * ga1 + bt1;
        tT[c0 * 68 + rla + 1] = (t0b - mb) * rsb * ga0 + bt0;
        tT[c1 * 68 + rla + 1] = (t1b - mb) * rsb * ga1 + bt1;
    }
    __syncthreads();

    // ---- MLP1 + relu -> hT (two col passes, fp16 weights) ----
#pragma unroll 1
    for (int pass = 0; pass < 2; pass++) {
        int h0 = lane + 64 * pass, h1 = lane + 32 + 64 * pass;
        U64 hacc[4][2];
        float bh0 = bb[64 + h0], bh1 = bb[64 + h1];
        U64 b0p = pack2(bh0, bh0), b1p = pack2(bh1, bh1);
#pragma unroll
        for (int p = 0; p < 4; p++) { hacc[p][0] = b0p; hacc[p][1] = b1p; }
#pragma unroll 4
        for (int k = 0; k < 64; k++) {
            const U64* xp = (const U64*)(trow + k * 68);
            float w0 = __half2float(w1h[h0 * 66 + k]);
            float w1v = __half2float(w1h[h1 * 66 + k]);
            U64 w0p = pack2(w0, w0), w1p = pack2(w1v, w1v);
#pragma unroll
            for (int p = 0; p < 4; p++) {
                U64 xv = xp[p];
                hacc[p][0] = fma2(xv, w0p, hacc[p][0]);
                hacc[p][1] = fma2(xv, w1p, hacc[p][1]);
            }
        }
#pragma unroll
        for (int p = 0; p < 4; p++) {
            int rla = warp * 8 + 2 * p;
            float a0, a1v, b0, b1v;
            unpack2(hacc[p][0], a0, b0);
            unpack2(hacc[p][1], a1v, b1v);
            hT[h0 * 68 + rla] = fmaxf(a0, 0.f);
            hT[h1 * 68 + rla] = fmaxf(a1v, 0.f);
            hT[h0 * 68 + rla + 1] = fmaxf(b0, 0.f);
            hT[h1 * 68 + rla + 1] = fmaxf(b1v, 0.f);
        }
    }
    __syncthreads();

    // ---- MLP2 + residual + LN2 -> out (fp16 weights) ----
    {
        U64 acc2[4][2];
        float bm0 = bb[192 + c0], bm1v = bb[192 + c1];
        U64 b0p = pack2(bm0, bm0), b1p = pack2(bm1v, bm1v);
#pragma unroll
        for (int p = 0; p < 4; p++) { acc2[p][0] = b0p; acc2[p][1] = b1p; }
        const float* hrow = hT + warp * 8;
#pragma unroll 4
        for (int k = 0; k < 128; k++) {
            const U64* xp = (const U64*)(hrow + k * 68);
            float w0 = __half2float(w2h[c0 * 130 + k]);
            float w1v = __half2float(w2h[c1 * 130 + k]);
            U64 w0p = pack2(w0, w0), w1p = pack2(w1v, w1v);
#pragma unroll
            for (int p = 0; p < 4; p++) {
                U64 xv = xp[p];
                acc2[p][0] = fma2(xv, w0p, acc2[p][0]);
                acc2[p][1] = fma2(xv, w1p, acc2[p][1]);
            }
        }
        float gb0 = bb[384 + c0], gb1 = bb[384 + c1];
        float bb0 = bb[448 + c0], bb1 = bb[448 + c1];
#pragma unroll
        for (int p = 0; p < 4; p++) {
            int rla = warp * 8 + 2 * p;
            long ra = rowbase + rla;
            float u0a, u0b, u1a, u1b;
            unpack2(acc2[p][0], u0a, u0b);
            unpack2(acc2[p][1], u1a, u1b);
            u0a += tT[c0 * 68 + rla];
            u1a += tT[c1 * 68 + rla];
            u0b += tT[c0 * 68 + rla + 1];
            u1b += tT[c1 * 68 + rla + 1];
            float sa = u0a + u1a, qa = u0a * u0a + u1a * u1a;
            float sb = u0b + u1b, qb = u0b * u0b + u1b * u1b;
#pragma unroll
            for (int off = 16; off; off >>= 1) {
                sa += __shfl_xor_sync(0xffffffffu, sa, off);
                qa += __shfl_xor_sync(0xffffffffu, qa, off);
                sb += __shfl_xor_sync(0xffffffffu, sb, off);
                qb += __shfl_xor_sync(0xffffffffu, qb, off);
            }
            float ma = sa * (1.f / 64.f), mb = sb * (1.f / 64.f);
            float rsa = rsqrtf(qa * (1.f / 64.f) - ma * ma + 1e-5f);
            float rsb = rsqrtf(qb * (1.f / 64.f) - mb * mb + 1e-5f);
            out[ra * 64 + c0] = (u0a - ma) * rsa * gb0 + bb0;
            out[ra * 64 + c1] = (u1a - ma) * rsa * gb1 + bb1;
            out[(ra + 1) * 64 + c0] = (u0b - mb) * rsb * gb0 + bb0;
            out[(ra + 1) * 64 + c1] = (u1b - mb) * rsb * gb1 + bb1;
        }
    }
}

extern "C" void kernel_launch(void* const* d_in, const int* in_sizes, int n_in, void* d_out,
                              int out_size) {
    const float* x = (const float*)d_in[0];
    const float* Wqkv = (const float*)d_in[4];
    const float* bqkv = (const float*)d_in[5];
    const float* Wout = (const float*)d_in[6];
    const float* bout = (const float*)d_in[7];
    const float* g1 = (const float*)d_in[8];
    const float* be1 = (const float*)d_in[9];
    const float* g2 = (const float*)d_in[10];
    const float* be2 = (const float*)d_in[11];
    const float* Wm1 = (const float*)d_in[12];
    const float* bm1 = (const float*)d_in[13];
    const float* Wm2 = (const float*)d_in[14];
    const float* bm2 = (const float*)d_in[15];
    float* out = (float*)d_out;

    cudaFuncSetAttribute(k_qkv, cudaFuncAttributeMaxDynamicSharedMemorySize, QKV_SMEM);
    cudaFuncSetAttribute(k_attn, cudaFuncAttributeMaxDynamicSharedMemorySize, ATTN_SMEM);
    cudaFuncSetAttribute(k_tail, cudaFuncAttributeMaxDynamicSharedMemorySize, TAIL_SMEM);

    k_qkv<<<dim3(128, 2), 512, QKV_SMEM>>>(x, Wqkv, bqkv);
    k_attn<<<1024, 256, ATTN_SMEM>>>();
    k_tail<<<256, 256, TAIL_SMEM>>>(x, Wout, bout, g1, be1, g2, be2, Wm1, bm1, Wm2, bm2, out);
}

// round 10
// speedup vs baseline: 1.3148x; 1.3148x over previous
#include <cuda_runtime.h>

#define N_TOK 16384
#define E_DIM 64
#define NHEAD 8
#define SEQ   1024
#define NBATCH 16

typedef unsigned long long U64;
typedef unsigned U32;

// scratch: fp16 Q/K/V in attention-native layouts; o in fp16 A-frag layout
__device__ U32 g_q[NBATCH * NHEAD * SEQ * 4];  // [b][h][q][dimpair]  (pre-scaled)
__device__ U32 g_k[NBATCH * NHEAD * SEQ * 4];  // [b][h][key][dimpair]
__device__ U32 g_v[NBATCH * NHEAD * 8 * 512];  // [b][h][dim][keypair]
__device__ U32 g_oh[N_TOK * 32];               // [row][dimpair] fp16

// ---------------- helpers ----------------
__device__ __forceinline__ U32 f2h2(float hi, float lo) {  // lo -> low half
    U32 r;
    asm("cvt.rn.f16x2.f32 %0, %1, %2;" : "=r"(r) : "f"(hi), "f"(lo));
    return r;
}
__device__ __forceinline__ U32 h2ex2(U32 x) {
    U32 r;
    asm("ex2.approx.f16x2 %0, %1;" : "=r"(r) : "r"(x));
    return r;
}
__device__ __forceinline__ U32 prmt(U32 a, U32 b, U32 sel) {
    U32 r;
    asm("prmt.b32 %0, %1, %2, %3;" : "=r"(r) : "r"(a), "r"(b), "r"(sel));
    return r;
}
// QK^T: m16n8k8, f16 inputs + f16 accumulators (C=0).
__device__ __forceinline__ void mma_qk_h(U32& d0, U32& d1, U32 a0, U32 a1, U32 b0) {
    asm("mma.sync.aligned.m16n8k8.row.col.f16.f16.f16.f16 "
        "{%0,%1},{%2,%3},{%4},{%5,%6};"
        : "=r"(d0), "=r"(d1)
        : "r"(a0), "r"(a1), "r"(b0), "r"(0u), "r"(0u));
}
// m16n8k16 f16 inputs, f32 accum (accumulating in place)
__device__ __forceinline__ void mma_16816(float& c0, float& c1, float& c2, float& c3,
                                          U32 a0, U32 a1, U32 a2, U32 a3, U32 b0, U32 b1) {
    asm("mma.sync.aligned.m16n8k16.row.col.f32.f16.f16.f32 "
        "{%0,%1,%2,%3},{%4,%5,%6,%7},{%8,%9},{%0,%1,%2,%3};"
        : "+f"(c0), "+f"(c1), "+f"(c2), "+f"(c3)
        : "r"(a0), "r"(a1), "r"(a2), "r"(a3), "r"(b0), "r"(b1));
}

// ================= Kernel 1: QKV projection via HMMA (unchanged) =================
#define QKV_SMEM ((128 * 36 + 96 * 36 + 128 * 35) * 4 + 192 * 4)
__global__ void __launch_bounds__(512) k_qkv(const float* __restrict__ x,
                                             const float* __restrict__ W,
                                             const float* __restrict__ bias) {
    extern __shared__ U32 smq[];
    U32* xh = smq;
    U32* wh = xh + 128 * 36;
    U32* vst = wh + 96 * 36;
    float* bs = (float*)(vst + 128 * 35);

    int tid = threadIdx.x;
    int warp = tid >> 5, lane = tid & 31;
    int rwarp = warp & 7, nthalf = warp >> 3;
    int g = lane >> 2, c = lane & 3;
    int y = blockIdx.y;
    int rowbase = blockIdx.x * 128;
    int bt = rowbase >> 10;
    int qloc = rowbase & 1023;

    const float4* x4 = (const float4*)x;
    for (int idx = tid; idx < 2048; idx += 512) {
        int row = idx >> 4, k4 = idx & 15;
        float4 v = x4[(long)(rowbase + row) * 16 + k4];
        xh[row * 36 + 2 * k4] = f2h2(v.y, v.x);
        xh[row * 36 + 2 * k4 + 1] = f2h2(v.w, v.z);
    }
    const float4* W4 = (const float4*)W;
    for (int idx = tid; idx < 1536; idx += 512) {
        int cc = idx >> 4, k4 = idx & 15;
        float4 v = W4[(y * 96 + cc) * 16 + k4];
        wh[cc * 36 + 2 * k4] = f2h2(v.y, v.x);
        wh[cc * 36 + 2 * k4 + 1] = f2h2(v.w, v.z);
    }
    if (tid < 192) bs[tid] = bias[tid];
    __syncthreads();

    int wr0 = rwarp * 16 + g, wr1 = wr0 + 8;
    U32 a[4][4];
#pragma unroll
    for (int ks = 0; ks < 4; ks++) {
        a[ks][0] = xh[wr0 * 36 + ks * 8 + c];
        a[ks][1] = xh[wr1 * 36 + ks * 8 + c];
        a[ks][2] = xh[wr0 * 36 + ks * 8 + c + 4];
        a[ks][3] = xh[wr1 * 36 + ks * 8 + c + 4];
    }

    const float SCL2 = 0.51010927915195162f;
#pragma unroll 1
    for (int ntl2 = 0; ntl2 < 6; ntl2++) {
        int ntl = nthalf * 6 + ntl2;
        int nt = y * 12 + ntl;
        float c0 = 0.f, c1 = 0.f, c2 = 0.f, c3 = 0.f;
        int ncol = ntl * 8 + g;
#pragma unroll
        for (int ks = 0; ks < 4; ks++) {
            U32 b0 = wh[ncol * 36 + ks * 8 + c];
            U32 b1 = wh[ncol * 36 + ks * 8 + c + 4];
            mma_16816(c0, c1, c2, c3, a[ks][0], a[ks][1], a[ks][2], a[ks][3], b0, b1);
        }
        int col0 = nt * 8 + 2 * c;
        float bv0 = bs[col0], bv1 = bs[col0 + 1];
        c0 += bv0; c1 += bv1; c2 += bv0; c3 += bv1;
        if (nt < 8) {
            long base = ((long)(bt * 8 + nt) * 1024 + qloc);
            g_q[(base + wr0) * 4 + c] = f2h2(c1 * SCL2, c0 * SCL2);
            g_q[(base + wr1) * 4 + c] = f2h2(c3 * SCL2, c2 * SCL2);
        } else if (nt < 16) {
            long base = ((long)(bt * 8 + (nt - 8)) * 1024 + qloc);
            g_k[(base + wr0) * 4 + c] = f2h2(c1, c0);
            g_k[(base + wr1) * 4 + c] = f2h2(c3, c2);
        } else {
            vst[wr0 * 35 + (nt - 16) * 4 + c] = f2h2(c1, c0);
            vst[wr1 * 35 + (nt - 16) * 4 + c] = f2h2(c3, c2);
        }
    }
    if (y == 1) {
        __syncthreads();
        int kpbase = qloc >> 1;
        for (int idx = tid; idx < 4096; idx += 512) {
            int d = idx >> 6, t = idx & 63;
            U32 w0 = vst[(2 * t) * 35 + (d >> 1)];
            U32 w1 = vst[(2 * t + 1) * 35 + (d >> 1)];
            U32 o = (d & 1) ? prmt(w0, w1, 0x7632u) : prmt(w0, w1, 0x5410u);
            g_v[((long)(bt * 8 + (d >> 3)) * 8 + (d & 7)) * 512 + kpbase + t] = o;
        }
    }
}

// ================= Kernel 2: attention (R7 mainloop; fp16 output) =================
#define ATTN_SMEM (1024 * 16 + 8 * 516 * 4)
__global__ void __launch_bounds__(256) k_attn() {
    extern __shared__ U32 smA[];
    U32* Ku = smA;            // [1024 key][4 words]
    U32* Vu = smA + 4096;     // [8 dim][516 keypair words]

    int tid = threadIdx.x;
    int warp = tid >> 5, lane = tid & 31;
    int g = lane >> 2, c = lane & 3;

    int bid = blockIdx.x;
    int b = bid >> 6;
    int h = (bid >> 3) & 7;
    int qt = bid & 7;

    const uint4* Ksrc = (const uint4*)(g_k + (long)(b * 8 + h) * 4096);
    const uint4* Vsrc = (const uint4*)(g_v + (long)(b * 8 + h) * 4096);
#pragma unroll
    for (int i = tid; i < 1024; i += 256) {
        ((uint4*)Ku)[i] = Ksrc[i];
        uint4 v = Vsrc[i];
        int dim = i >> 7, kp = (i & 127) << 2;
        *(uint4*)(Vu + dim * 516 + kp) = v;
    }

    int qloc0 = qt * 128 + warp * 16 + g;
    int qloc1 = qloc0 + 8;
    long qb = (long)(b * 8 + h) * 1024;
    U32 aq0 = g_q[(qb + qloc0) * 4 + c];
    U32 aq1 = g_q[(qb + qloc1) * 4 + c];

    float acc0 = 0.f, acc1 = 0.f, acc2 = 0.f, acc3 = 0.f;
    float la0 = 0.f, la1 = 0.f, lb2 = 0.f, lb3 = 0.f;
    const U32 ONES = 0x3C003C00u;  // half2(1.0, 1.0)
    __syncthreads();

    const U32* Kg = Ku + g * 4 + c;
    const U32* Vg = Vu + g * 516 + c;
#pragma unroll 1
    for (int jo = 0; jo < 8; jo++) {
#pragma unroll
        for (int ji = 0; ji < 8; ji++) {
            int n = jo * 128 + ji * 16;
            U32 kb0 = Kg[n * 4];
            U32 kb1 = Kg[(n + 8) * 4];
            U32 s0, s1, s2, s3;
            mma_qk_h(s0, s1, aq0, aq1, kb0);
            mma_qk_h(s2, s3, aq0, aq1, kb1);
            U32 p0 = h2ex2(s0);
            U32 p1 = h2ex2(s1);
            U32 p2 = h2ex2(s2);
            U32 p3 = h2ex2(s3);
            U32 vb0 = Vg[n >> 1];
            U32 vb1 = Vg[(n >> 1) + 4];
            mma_16816(acc0, acc1, acc2, acc3, p0, p1, p2, p3, vb0, vb1);
            mma_16816(la0, la1, lb2, lb3, p0, p1, p2, p3, ONES, ONES);
        }
    }

    float invA = __fdividef(1.0f, la0);
    float invB = __fdividef(1.0f, lb2);

    int r0 = b * SEQ + qloc0, r1 = b * SEQ + qloc1;
    // fp16 A-frag layout: [row][dimpair], dimpair = 4h + c covers dims 8h+2c, +1
    g_oh[(long)r0 * 32 + 4 * h + c] = f2h2(acc1 * invA, acc0 * invA);
    g_oh[(long)r1 * 32 + 4 * h + c] = f2h2(acc3 * invB, acc2 * invB);
}

// ================= Kernel 3: all-HMMA fused tail =================
// grid 128, 256 threads = 8 warps x 16 rows. Everything register-resident:
// out-proj (32 HMMA) -> +x+bias, LN1 -> MLP1 (64) -> relu -> MLP2 (64) -> +mi, LN2.
// C-frag of stage N == A-frag of stage N+1 (n-tile 2ks+j supplies k-slice 16ks+8j).
#define TAIL_SMEM ((4608 + 8704 + 2304 + 4608 + 4352 + 512) * 4)
__global__ void __launch_bounds__(256) k_tail(
    const float* __restrict__ x, const float* __restrict__ Wout, const float* __restrict__ bout,
    const float* __restrict__ g1, const float* __restrict__ be1, const float* __restrict__ g2,
    const float* __restrict__ be2, const float* __restrict__ Wm1, const float* __restrict__ bm1,
    const float* __restrict__ Wm2, const float* __restrict__ bm2, float* __restrict__ out) {
    extern __shared__ U32 smT[];
    U32* oh = smT;                       // [128 row][36]  o fp16 pairs
    float* xs = (float*)(smT + 4608);    // [128 row][68]  x f32
    U32* wo = smT + 13312;               // [64 n][36]     Wout fp16 pairs
    U32* w1 = smT + 15616;               // [128 n][36]    Wm1
    U32* w2 = smT + 20224;               // [64 n][68]     Wm2
    float* bb = (float*)(smT + 24576);   // [512] biases/ln params

    int tid = threadIdx.x;
    int warp = tid >> 5, lane = tid & 31;
    int g = lane >> 2, c = lane & 3;
    int rowbase = blockIdx.x * 128;

    // ---- staging ----
    const uint4* oh4 = (const uint4*)g_oh;
    for (int idx = tid; idx < 1024; idx += 256) {
        int row = idx >> 3, k4 = idx & 7;
        *(uint4*)(oh + row * 36 + k4 * 4) = oh4[(long)(rowbase + row) * 8 + k4];
    }
    const float4* x4 = (const float4*)x;
    for (int idx = tid; idx < 2048; idx += 256) {
        int row = idx >> 4, k4 = idx & 15;
        *(float4*)(xs + row * 68 + k4 * 4) = x4[(long)(rowbase + row) * 16 + k4];
    }
    const float4* Wo4 = (const float4*)Wout;
    for (int idx = tid; idx < 1024; idx += 256) {
        int cc = idx >> 4, k4 = idx & 15;
        float4 v = Wo4[idx];
        wo[cc * 36 + 2 * k4] = f2h2(v.y, v.x);
        wo[cc * 36 + 2 * k4 + 1] = f2h2(v.w, v.z);
    }
    const float4* W14 = (const float4*)Wm1;
    for (int idx = tid; idx < 2048; idx += 256) {
        int cc = idx >> 4, k4 = idx & 15;
        float4 v = W14[idx];
        w1[cc * 36 + 2 * k4] = f2h2(v.y, v.x);
        w1[cc * 36 + 2 * k4 + 1] = f2h2(v.w, v.z);
    }
    const float4* W24 = (const float4*)Wm2;
    for (int idx = tid; idx < 2048; idx += 256) {
        int cc = idx >> 5, k4 = idx & 31;
        float4 v = W24[idx];
        w2[cc * 68 + 2 * k4] = f2h2(v.y, v.x);
        w2[cc * 68 + 2 * k4 + 1] = f2h2(v.w, v.z);
    }
    if (tid < 64) bb[tid] = bout[tid];
    if (tid < 128) bb[64 + tid] = bm1[tid];
    if (tid < 64) {
        bb[192 + tid] = bm2[tid];
        bb[256 + tid] = g1[tid];
        bb[320 + tid] = be1[tid];
        bb[384 + tid] = g2[tid];
        bb[448 + tid] = be2[tid];
    }
    __syncthreads();

    int wr0 = warp * 16 + g, wr1 = wr0 + 8;

    // ---- out-proj: [128,64] x Wout^T[64,64], 32 HMMA ----
    float tC[8][4];
#pragma unroll
    for (int nt = 0; nt < 8; nt++)
#pragma unroll
        for (int j = 0; j < 4; j++) tC[nt][j] = 0.f;
#pragma unroll
    for (int ks = 0; ks < 4; ks++) {
        U32 a0 = oh[wr0 * 36 + 8 * ks + c];
        U32 a1 = oh[wr1 * 36 + 8 * ks + c];
        U32 a2 = oh[wr0 * 36 + 8 * ks + 4 + c];
        U32 a3 = oh[wr1 * 36 + 8 * ks + 4 + c];
#pragma unroll
        for (int nt = 0; nt < 8; nt++) {
            U32 b0 = wo[(8 * nt + g) * 36 + 8 * ks + c];
            U32 b1 = wo[(8 * nt + g) * 36 + 8 * ks + 4 + c];
            mma_16816(tC[nt][0], tC[nt][1], tC[nt][2], tC[nt][3], a0, a1, a2, a3, b0, b1);
        }
    }

    // ---- + bout + x, LN1 ----
    float s0 = 0.f, q0 = 0.f, s1 = 0.f, q1 = 0.f;
#pragma unroll
    for (int nt = 0; nt < 8; nt++) {
        int col0 = 8 * nt + 2 * c;
        float2 xv0 = *(float2*)(xs + wr0 * 68 + col0);
        float2 xv1 = *(float2*)(xs + wr1 * 68 + col0);
        float bo0 = bb[col0], bo1 = bb[col0 + 1];
        tC[nt][0] += bo0 + xv0.x;
        tC[nt][1] += bo1 + xv0.y;
        tC[nt][2] += bo0 + xv1.x;
        tC[nt][3] += bo1 + xv1.y;
        s0 += tC[nt][0] + tC[nt][1];
        q0 += tC[nt][0] * tC[nt][0] + tC[nt][1] * tC[nt][1];
        s1 += tC[nt][2] + tC[nt][3];
        q1 += tC[nt][2] * tC[nt][2] + tC[nt][3] * tC[nt][3];
    }
    s0 += __shfl_xor_sync(0xffffffffu, s0, 1);
    s0 += __shfl_xor_sync(0xffffffffu, s0, 2);
    q0 += __shfl_xor_sync(0xffffffffu, q0, 1);
    q0 += __shfl_xor_sync(0xffffffffu, q0, 2);
    s1 += __shfl_xor_sync(0xffffffffu, s1, 1);
    s1 += __shfl_xor_sync(0xffffffffu, s1, 2);
    q1 += __shfl_xor_sync(0xffffffffu, q1, 1);
    q1 += __shfl_xor_sync(0xffffffffu, q1, 2);
    float m0 = s0 * (1.f / 64.f), m1 = s1 * (1.f / 64.f);
    float rs0 = rsqrtf(q0 * (1.f / 64.f) - m0 * m0 + 1e-5f);
    float rs1 = rsqrtf(q1 * (1.f / 64.f) - m1 * m1 + 1e-5f);

    float mi[8][4];
#pragma unroll
    for (int nt = 0; nt < 8; nt++) {
        int col0 = 8 * nt + 2 * c;
        float ga0 = bb[256 + col0], ga1 = bb[257 + col0];
        float be0 = bb[320 + col0], be1v = bb[321 + col0];
        mi[nt][0] = (tC[nt][0] - m0) * rs0 * ga0 + be0;
        mi[nt][1] = (tC[nt][1] - m0) * rs0 * ga1 + be1v;
        mi[nt][2] = (tC[nt][2] - m1) * rs1 * ga0 + be0;
        mi[nt][3] = (tC[nt][3] - m1) * rs1 * ga1 + be1v;
    }
    // A-fragments for MLP1 (k-step ks uses n-tiles 2ks, 2ks+1)
    U32 aM[4][4];
#pragma unroll
    for (int ks = 0; ks < 4; ks++) {
        aM[ks][0] = f2h2(mi[2 * ks][1], mi[2 * ks][0]);
        aM[ks][1] = f2h2(mi[2 * ks][3], mi[2 * ks][2]);
        aM[ks][2] = f2h2(mi[2 * ks + 1][1], mi[2 * ks + 1][0]);
        aM[ks][3] = f2h2(mi[2 * ks + 1][3], mi[2 * ks + 1][2]);
    }

    // ---- MLP1 (+relu) and MLP2 accumulation, in two h-halves ----
    float uC[8][4];
#pragma unroll
    for (int nt = 0; nt < 8; nt++)
#pragma unroll
        for (int j = 0; j < 4; j++) uC[nt][j] = 0.f;

#pragma unroll
    for (int H = 0; H < 2; H++) {
        float hC[8][4];
#pragma unroll
        for (int nt = 0; nt < 8; nt++)
#pragma unroll
            for (int j = 0; j < 4; j++) hC[nt][j] = 0.f;
#pragma unroll
        for (int ks = 0; ks < 4; ks++) {
#pragma unroll
            for (int nt = 0; nt < 8; nt++) {
                U32 b0 = w1[(64 * H + 8 * nt + g) * 36 + 8 * ks + c];
                U32 b1 = w1[(64 * H + 8 * nt + g) * 36 + 8 * ks + 4 + c];
                mma_16816(hC[nt][0], hC[nt][1], hC[nt][2], hC[nt][3],
                          aM[ks][0], aM[ks][1], aM[ks][2], aM[ks][3], b0, b1);
            }
        }
        // + bm1, relu
#pragma unroll
        for (int nt = 0; nt < 8; nt++) {
            int hcol0 = 64 * H + 8 * nt + 2 * c;
            float bh0 = bb[64 + hcol0], bh1 = bb[65 + hcol0];
            hC[nt][0] = fmaxf(hC[nt][0] + bh0, 0.f);
            hC[nt][1] = fmaxf(hC[nt][1] + bh1, 0.f);
            hC[nt][2] = fmaxf(hC[nt][2] + bh0, 0.f);
            hC[nt][3] = fmaxf(hC[nt][3] + bh1, 0.f);
        }
        // MLP2 k-steps 4H..4H+3
#pragma unroll
        for (int ks2 = 0; ks2 < 4; ks2++) {
            U32 a0 = f2h2(hC[2 * ks2][1], hC[2 * ks2][0]);
            U32 a1 = f2h2(hC[2 * ks2][3], hC[2 * ks2][2]);
            U32 a2 = f2h2(hC[2 * ks2 + 1][1], hC[2 * ks2 + 1][0]);
            U32 a3 = f2h2(hC[2 * ks2 + 1][3], hC[2 * ks2 + 1][2]);
#pragma unroll
            for (int nt3 = 0; nt3 < 8; nt3++) {
                U32 b0 = w2[(8 * nt3 + g) * 68 + 8 * (4 * H + ks2) + c];
                U32 b1 = w2[(8 * nt3 + g) * 68 + 8 * (4 * H + ks2) + 4 + c];
                mma_16816(uC[nt3][0], uC[nt3][1], uC[nt3][2], uC[nt3][3], a0, a1, a2, a3, b0, b1);
            }
        }
    }

    // ---- + bm2 + mi residual, LN2, store ----
    float t0 = 0.f, r0q = 0.f, t1 = 0.f, r1q = 0.f;
#pragma unroll
    for (int nt = 0; nt < 8; nt++) {
        int col0 = 8 * nt + 2 * c;
        float bm0 = bb[192 + col0], bm1v = bb[193 + col0];
        uC[nt][0] += bm0 + mi[nt][0];
        uC[nt][1] += bm1v + mi[nt][1];
        uC[nt][2] += bm0 + mi[nt][2];
        uC[nt][3] += bm1v + mi[nt][3];
        t0 += uC[nt][0] + uC[nt][1];
        r0q += uC[nt][0] * uC[nt][0] + uC[nt][1] * uC[nt][1];
        t1 += uC[nt][2] + uC[nt][3];
        r1q += uC[nt][2] * uC[nt][2] + uC[nt][3] * uC[nt][3];
    }
    t0 += __shfl_xor_sync(0xffffffffu, t0, 1);
    t0 += __shfl_xor_sync(0xffffffffu, t0, 2);
    r0q += __shfl_xor_sync(0xffffffffu, r0q, 1);
    r0q += __shfl_xor_sync(0xffffffffu, r0q, 2);
    t1 += __shfl_xor_sync(0xffffffffu, t1, 1);
    t1 += __shfl_xor_sync(0xffffffffu, t1, 2);
    r1q += __shfl_xor_sync(0xffffffffu, r1q, 1);
    r1q += __shfl_xor_sync(0xffffffffu, r1q, 2);
    float mu0 = t0 * (1.f / 64.f), mu1 = t1 * (1.f / 64.f);
    float rz0 = rsqrtf(r0q * (1.f / 64.f) - mu0 * mu0 + 1e-5f);
    float rz1 = rsqrtf(r1q * (1.f / 64.f) - mu1 * mu1 + 1e-5f);

    long ro0 = (long)(rowbase + wr0) * 64;
    long ro1 = (long)(rowbase + wr1) * 64;
#pragma unroll
    for (int nt = 0; nt < 8; nt++) {
        int col0 = 8 * nt + 2 * c;
        float gb0 = bb[384 + col0], gb1 = bb[385 + col0];
        float bz0 = bb[448 + col0], bz1 = bb[449 + col0];
        *(float2*)(out + ro0 + col0) =
            make_float2((uC[nt][0] - mu0) * rz0 * gb0 + bz0, (uC[nt][1] - mu0) * rz0 * gb1 + bz1);
        *(float2*)(out + ro1 + col0) =
            make_float2((uC[nt][2] - mu1) * rz1 * gb0 + bz0, (uC[nt][3] - mu1) * rz1 * gb1 + bz1);
    }
}

extern "C" void kernel_launch(void* const* d_in, const int* in_sizes, int n_in, void* d_out,
                              int out_size) {
    const float* x = (const float*)d_in[0];
    const float* Wqkv = (const float*)d_in[4];
    const float* bqkv = (const float*)d_in[5];
    const float* Wout = (const float*)d_in[6];
    const float* bout = (const float*)d_in[7];
    const float* g1 = (const float*)d_in[8];
    const float* be1 = (const float*)d_in[9];
    const float* g2 = (const float*)d_in[10];
    const float* be2 = (const float*)d_in[11];
    const float* Wm1 = (const float*)d_in[12];
    const float* bm1 = (const float*)d_in[13];
    const float* Wm2 = (const float*)d_in[14];
    const float* bm2 = (const float*)d_in[15];
    float* out = (float*)d_out;

    cudaFuncSetAttribute(k_qkv, cudaFuncAttributeMaxDynamicSharedMemorySize, QKV_SMEM);
    cudaFuncSetAttribute(k_attn, cudaFuncAttributeMaxDynamicSharedMemorySize, ATTN_SMEM);
    cudaFuncSetAttribute(k_tail, cudaFuncAttributeMaxDynamicSharedMemorySize, TAIL_SMEM);

    k_qkv<<<dim3(128, 2), 512, QKV_SMEM>>>(x, Wqkv, bqkv);
    k_attn<<<1024, 256, ATTN_SMEM>>>();
    k_tail<<<128, 256, TAIL_SMEM>>>(x, Wout, bout, g1, be1, g2, be2, Wm1, bm1, Wm2, bm2, out);
}